// round 2
// baseline (speedup 1.0000x reference)
#include <cuda_runtime.h>
#include <cstdint>

#define BATCH 2
#define MPTS  5000
#define CH    128
#define KSPP  50
#define NSAMP 2000
#define KNN   1000
#define EPSF  1e-8f

// 80 MB scratch for one branch's d2-partial (bb[m] - 2*dot), reused across branches.
__device__ __align__(16) float g_d2[(size_t)BATCH * NSAMP * MPTS];
// squared norms of feat rows: [branch][b][m]
__device__ __align__(16) float g_bb[2 * BATCH * MPTS];
// accumulators: 0=dist sim sum, 1=ortho sse, 2=bij sse, 3=res sse
__device__ float g_acc[4];

// ---------- packed f32x2 helpers (Blackwell FFMA2) ----------
__device__ __forceinline__ unsigned long long pack2(float x, float y) {
    unsigned long long r;
    asm("mov.b64 %0, {%1, %2};" : "=l"(r) : "f"(x), "f"(y));
    return r;
}
__device__ __forceinline__ void fma2(unsigned long long& d, unsigned long long a,
                                     unsigned long long b) {
    asm("fma.rn.f32x2 %0, %1, %2, %0;" : "+l"(d) : "l"(a), "l"(b));
}
__device__ __forceinline__ void unpack2(unsigned long long v, float& lo, float& hi) {
    asm("mov.b64 {%0, %1}, %2;" : "=f"(lo), "=f"(hi) : "l"(v));
}

__device__ __forceinline__ float warp_sum(float v) {
    #pragma unroll
    for (int o = 16; o; o >>= 1) v += __shfl_xor_sync(0xffffffffu, v, o);
    return v;
}

// ---------- kernel 1: row norms for both feats + zero accumulators ----------
__global__ void init_norms(const float* __restrict__ f1, const float* __restrict__ f2) {
    if (blockIdx.x == 0 && threadIdx.x < 4) g_acc[threadIdx.x] = 0.f;
    int w = blockIdx.x * 8 + (threadIdx.x >> 5);
    int lane = threadIdx.x & 31;
    if (w >= 2 * BATCH * MPTS) return;
    int branch = w / (BATCH * MPTS);
    int bm = w % (BATCH * MPTS);
    const float* f = (branch ? f2 : f1) + (size_t)bm * CH + lane * 4;
    float4 v = *reinterpret_cast<const float4*>(f);
    float ss = v.x * v.x + v.y * v.y + v.z * v.z + v.w * v.w;
    ss = warp_sum(ss);
    if (lane == 0) g_bb[branch * (BATCH * MPTS) + bm] = ss;
}

// ---------- kernel 2: d2-partial GEMM: g_d2[b][n][m] = bb[m] - 2 * <f1[n], feat[m]> ----------
// 128x128 tile, K=128, BK=8, 256 threads, 8x8 per thread via fma.rn.f32x2 (FFMA2).
// Double-buffered smem: one barrier per k-step, prefetch overlapped with compute.
__global__ __launch_bounds__(256, 2) void gemm_d2(const float* __restrict__ feat,
                                                  const int* __restrict__ ridx,
                                                  int branch) {
    __shared__ __align__(16) float As[2][8][128];
    __shared__ __align__(16) float Bs[2][8][128];
    int tid = threadIdx.x;
    int bx = blockIdx.x, by = blockIdx.y, bz = blockIdx.z;
    const float* fb = feat + (size_t)bz * MPTS * CH;
    const float* bbp = g_bb + branch * (BATCH * MPTS) + bz * MPTS;

    // global->smem load assignment: thread loads one float4 of A and one of B per k-block
    int lrow = tid >> 1;
    int lk4  = (tid & 1) * 4;
    int an = by * 128 + lrow;
    bool aval = an < NSAMP;
    const float* aptr = fb + (size_t)(aval ? ridx[an] : 0) * CH + lk4;
    int bm = bx * 128 + lrow;
    bool bval = bm < MPTS;
    const float* bptr = fb + (size_t)(bval ? bm : 0) * CH + lk4;

    int tx = tid & 15, ty = tid >> 4;
    int tx4 = tx * 4, ty4 = ty * 4;

    unsigned long long acc[8][4];
    #pragma unroll
    for (int i = 0; i < 8; i++)
        #pragma unroll
        for (int j = 0; j < 4; j++) acc[i][j] = 0ull;

    // preload k-block 0 into buffer 0
    {
        float4 av = aval ? *reinterpret_cast<const float4*>(aptr)
                         : make_float4(0.f, 0.f, 0.f, 0.f);
        float4 bv = bval ? *reinterpret_cast<const float4*>(bptr)
                         : make_float4(0.f, 0.f, 0.f, 0.f);
        As[0][lk4 + 0][lrow] = av.x; As[0][lk4 + 1][lrow] = av.y;
        As[0][lk4 + 2][lrow] = av.z; As[0][lk4 + 3][lrow] = av.w;
        Bs[0][lk4 + 0][lrow] = bv.x; Bs[0][lk4 + 1][lrow] = bv.y;
        Bs[0][lk4 + 2][lrow] = bv.z; Bs[0][lk4 + 3][lrow] = bv.w;
    }
    __syncthreads();

    #pragma unroll 2
    for (int kb = 0; kb < 16; ++kb) {
        int buf = kb & 1;
        float4 av2, bv2;
        if (kb < 15) {
            av2 = aval ? *reinterpret_cast<const float4*>(aptr + (kb + 1) * 8)
                       : make_float4(0.f, 0.f, 0.f, 0.f);
            bv2 = bval ? *reinterpret_cast<const float4*>(bptr + (kb + 1) * 8)
                       : make_float4(0.f, 0.f, 0.f, 0.f);
        }
        #pragma unroll
        for (int kk = 0; kk < 8; kk++) {
            float4 a0 = *reinterpret_cast<const float4*>(&As[buf][kk][ty4]);
            float4 a1 = *reinterpret_cast<const float4*>(&As[buf][kk][64 + ty4]);
            float4 b0 = *reinterpret_cast<const float4*>(&Bs[buf][kk][tx4]);
            float4 b1 = *reinterpret_cast<const float4*>(&Bs[buf][kk][64 + tx4]);
            unsigned long long bp[4] = {pack2(b0.x, b0.y), pack2(b0.z, b0.w),
                                        pack2(b1.x, b1.y), pack2(b1.z, b1.w)};
            float ar[8] = {a0.x, a0.y, a0.z, a0.w, a1.x, a1.y, a1.z, a1.w};
            #pragma unroll
            for (int i = 0; i < 8; i++) {
                unsigned long long ad = pack2(ar[i], ar[i]);
                #pragma unroll
                for (int j = 0; j < 4; j++) fma2(acc[i][j], ad, bp[j]);
            }
        }
        if (kb < 15) {
            int nb = buf ^ 1;
            As[nb][lk4 + 0][lrow] = av2.x; As[nb][lk4 + 1][lrow] = av2.y;
            As[nb][lk4 + 2][lrow] = av2.z; As[nb][lk4 + 3][lrow] = av2.w;
            Bs[nb][lk4 + 0][lrow] = bv2.x; Bs[nb][lk4 + 1][lrow] = bv2.y;
            Bs[nb][lk4 + 2][lrow] = bv2.z; Bs[nb][lk4 + 3][lrow] = bv2.w;
            __syncthreads();
        }
    }

    // epilogue: d2_partial = bb[m] - 2*dot, vectorized stores
    int n0 = by * 128 + ty4;
    int m0 = bx * 128 + tx4;
    int m1 = m0 + 64;
    float4 bb0 = make_float4(0.f, 0.f, 0.f, 0.f), bb1 = bb0;
    if (m0 < MPTS) bb0 = *reinterpret_cast<const float4*>(bbp + m0);
    if (m1 < MPTS) bb1 = *reinterpret_cast<const float4*>(bbp + m1);
    #pragma unroll
    for (int i = 0; i < 8; i++) {
        int n = (i < 4) ? (n0 + i) : (n0 + 64 + i - 4);
        if (n >= NSAMP) continue;
        float* orow = g_d2 + ((size_t)bz * NSAMP + n) * MPTS;
        float d[8];
        #pragma unroll
        for (int j = 0; j < 4; j++) { unpack2(acc[i][j], d[j * 2], d[j * 2 + 1]); }
        if (m0 < MPTS) {
            float4 o;
            o.x = fmaf(-2.f, d[0], bb0.x); o.y = fmaf(-2.f, d[1], bb0.y);
            o.z = fmaf(-2.f, d[2], bb0.z); o.w = fmaf(-2.f, d[3], bb0.w);
            *reinterpret_cast<float4*>(orow + m0) = o;
        }
        if (m1 < MPTS) {
            float4 o;
            o.x = fmaf(-2.f, d[4], bb1.x); o.y = fmaf(-2.f, d[5], bb1.y);
            o.z = fmaf(-2.f, d[6], bb1.z); o.w = fmaf(-2.f, d[7], bb1.w);
            *reinterpret_cast<float4*>(orow + m1) = o;
        }
    }
}

// ---------- kernel 3: per-row exact k=1000 radix select + cosine reduction ----------
// Warp-aggregated histogram atomics + warp-parallel cumsum (exponent bins are
// heavily skewed for this data, so naive per-key atomics serialize 32-way).
#define PAD_ITERS 5120   // MPTS rounded up to a multiple of 256 (barrier-safe trip count)

__global__ __launch_bounds__(256) void select_reduce(const float* __restrict__ dist,
                                                     const int* __restrict__ ridx,
                                                     int branch) {
    __shared__ __align__(16) unsigned int keys[MPTS];
    __shared__ unsigned int hist[256];
    __shared__ unsigned int sh_P;
    __shared__ int sh_r;
    __shared__ int sh_eq;
    __shared__ float red[96];

    int tid = threadIdx.x;
    int lane = tid & 31;
    int b = blockIdx.x / NSAMP;
    int n = blockIdx.x % NSAMP;
    int col = ridx[n];
    float aa = g_bb[branch * (BATCH * MPTS) + b * MPTS + col];
    const float* rowp = g_d2 + (size_t)blockIdx.x * MPTS;

    // load row, add aa, clamp to >= 0 (bit pattern then orders correctly)
    for (int q = tid; q < MPTS / 4; q += 256) {
        float4 v = reinterpret_cast<const float4*>(rowp)[q];
        uint4 k;
        k.x = __float_as_uint(fmaxf(v.x + aa, 0.f));
        k.y = __float_as_uint(fmaxf(v.y + aa, 0.f));
        k.z = __float_as_uint(fmaxf(v.z + aa, 0.f));
        k.w = __float_as_uint(fmaxf(v.w + aa, 0.f));
        reinterpret_cast<uint4*>(keys)[q] = k;
    }
    if (tid == 0) { sh_P = 0; sh_r = KNN; sh_eq = 0; }
    __syncthreads();

    // 4-pass MSD radix select for the exact 1000th-smallest key
    #pragma unroll
    for (int pass = 0; pass < 4; ++pass) {
        int shift = 24 - 8 * pass;
        unsigned int P = sh_P;
        unsigned int pmask = (pass == 0) ? 0u : (0xFFFFFFFFu << ((shift + 8) & 31));
        hist[tid] = 0;
        __syncthreads();
        // warp-aggregated histogram: one atomic per distinct bin per warp
        for (int i = tid; i < PAD_ITERS; i += 256) {
            bool inb = i < MPTS;
            unsigned int k = inb ? keys[i] : 0u;
            bool active = inb && ((k & pmask) == P);
            unsigned int m = __ballot_sync(0xffffffffu, active);
            if (active) {
                int bin = (k >> shift) & 255;
                unsigned int peers = __match_any_sync(m, bin);
                if (lane == __ffs(peers) - 1)
                    atomicAdd(&hist[bin], __popc(peers));
            }
        }
        __syncthreads();
        // warp 0: parallel cumsum over 256 bins (8 per lane) + bin find
        if (tid < 32) {
            unsigned int c[8];
            unsigned int s = 0;
            int base = tid * 8;
            #pragma unroll
            for (int j = 0; j < 8; j++) { c[j] = hist[base + j]; s += c[j]; }
            unsigned int inc = s;
            #pragma unroll
            for (int o = 1; o < 32; o <<= 1) {
                unsigned int v = __shfl_up_sync(0xffffffffu, inc, o);
                if (tid >= o) inc += v;
            }
            unsigned int excl = inc - s;
            unsigned int r = (unsigned int)sh_r;
            if (r > excl && r <= inc) {   // exactly one lane qualifies
                unsigned int cum = excl;
                #pragma unroll
                for (int j = 0; j < 8; j++) {
                    if (cum + c[j] >= r) {
                        sh_P = P | ((unsigned int)(base + j) << shift);
                        sh_r = (int)(r - cum);
                        break;
                    }
                    cum += c[j];
                }
            }
        }
        __syncthreads();
    }
    unsigned int T = sh_P;   // key of the 1000th smallest
    int need_eq = sh_r;      // how many ties at T to include

    const float* dcol = dist + (size_t)b * MPTS * MPTS + col;
    float num = 0.f, s1 = 0.f, s2 = 0.f;
    for (int i = tid; i < MPTS; i += 256) {
        unsigned int k = keys[i];
        bool take = (k < T);
        if (!take && k == T) take = (atomicAdd(&sh_eq, 1) < need_eq);
        if (take) {
            float dr = sqrtf(fmaxf(__uint_as_float(k), 1e-12f));
            float df = __ldg(dcol + (size_t)i * MPTS);
            num = fmaf(dr, df, num);
            s1  = fmaf(dr, dr, s1);
            s2  = fmaf(df, df, s2);
        }
    }
    num = warp_sum(num); s1 = warp_sum(s1); s2 = warp_sum(s2);
    int w = tid >> 5;
    if (lane == 0) { red[w] = num; red[32 + w] = s1; red[64 + w] = s2; }
    __syncthreads();
    if (tid == 0) {
        float N = 0.f, S1 = 0.f, S2 = 0.f;
        #pragma unroll
        for (int i = 0; i < 8; i++) { N += red[i]; S1 += red[32 + i]; S2 += red[64 + i]; }
        float den = fmaxf(sqrtf(S1), EPSF) * fmaxf(sqrtf(S2), EPSF);
        float sim = 1.f - fabsf(N / den);
        atomicAdd(&g_acc[0], sim);
    }
}

// ---------- kernel 4: ortho / bij / res losses on the 50x50 matrices ----------
__global__ void small_losses(const float* __restrict__ A0, const float* __restrict__ A1,
                             const float* __restrict__ A2, const float* __restrict__ A3) {
    __shared__ float shA[KSPP * KSPP];
    __shared__ float shB[KSPP * KSPP];
    __shared__ float red[8];
    int t = blockIdx.x, b = blockIdx.y, tid = threadIdx.x;
    const float* mats[4] = {A0, A1, A2, A3};
    size_t off = (size_t)b * KSPP * KSPP;
    float local = 0.f;
    if (t == 6) {
        for (int e = tid; e < KSPP * KSPP; e += 256) {
            float d1 = A0[off + e] - A2[off + e];
            float d2 = A1[off + e] - A3[off + e];
            local += d1 * d1 + d2 * d2;
        }
    } else {
        int ai, bi; bool tb;
        switch (t) {
            case 0: ai = 0; bi = 0; tb = true;  break;
            case 1: ai = 1; bi = 1; tb = true;  break;
            case 2: ai = 2; bi = 2; tb = true;  break;
            case 3: ai = 3; bi = 3; tb = true;  break;
            case 4: ai = 0; bi = 1; tb = false; break;
            default: ai = 1; bi = 0; tb = false; break;
        }
        for (int e = tid; e < KSPP * KSPP; e += 256) {
            shA[e] = mats[ai][off + e];
            shB[e] = mats[bi][off + e];
        }
        __syncthreads();
        for (int e = tid; e < KSPP * KSPP; e += 256) {
            int i = e / KSPP, j = e % KSPP;
            float dot = 0.f;
            if (tb) {
                for (int k = 0; k < KSPP; k++) dot = fmaf(shA[i * KSPP + k], shB[j * KSPP + k], dot);
            } else {
                for (int k = 0; k < KSPP; k++) dot = fmaf(shA[i * KSPP + k], shB[k * KSPP + j], dot);
            }
            float diff = dot - (i == j ? 1.f : 0.f);
            local += diff * diff;
        }
    }
    local = warp_sum(local);
    if ((tid & 31) == 0) red[tid >> 5] = local;
    __syncthreads();
    if (tid == 0) {
        float s = 0.f;
        #pragma unroll
        for (int i = 0; i < 8; i++) s += red[i];
        int slot = (t < 4) ? 1 : ((t < 6) ? 2 : 3);
        atomicAdd(&g_acc[slot], s);
    }
}

// ---------- kernel 5: combine ----------
__global__ void finalize(float* __restrict__ out) {
    float dist  = g_acc[0] * 0.5f;
    float ortho = g_acc[1] / (float)BATCH * 0.5f;
    float bij   = g_acc[2] / (float)BATCH;
    float res   = g_acc[3] / (float)BATCH;
    out[0] = dist + ortho + bij + res;
    out[1] = ortho;
    out[2] = bij;
    out[3] = res;
    out[4] = dist;
}

extern "C" void kernel_launch(void* const* d_in, const int* in_sizes, int n_in,
                              void* d_out, int out_size) {
    const float* C12   = (const float*)d_in[0];
    const float* C21   = (const float*)d_in[1];
    const float* C12n  = (const float*)d_in[2];
    const float* C21n  = (const float*)d_in[3];
    const float* feat1 = (const float*)d_in[4];
    const float* feat2 = (const float*)d_in[5];
    // d_in[6], d_in[7] (evecs_trans) unused by the reference
    const float* dist1 = (const float*)d_in[8];
    const float* dist2 = (const float*)d_in[9];
    const int*   ri1   = (const int*)d_in[10];
    const int*   ri2   = (const int*)d_in[11];
    float* out = (float*)d_out;

    init_norms<<<2500, 256>>>(feat1, feat2);

    dim3 ggrid((MPTS + 127) / 128, (NSAMP + 127) / 128, BATCH);  // 40 x 16 x 2
    gemm_d2<<<ggrid, 256>>>(feat1, ri1, 0);
    select_reduce<<<BATCH * NSAMP, 256>>>(dist1, ri1, 0);
    gemm_d2<<<ggrid, 256>>>(feat2, ri2, 1);
    select_reduce<<<BATCH * NSAMP, 256>>>(dist2, ri2, 1);

    small_losses<<<dim3(7, BATCH), 256>>>(C12, C21, C12n, C21n);
    finalize<<<1, 1>>>(out);
}

// round 3
// speedup vs baseline: 1.3937x; 1.3937x over previous
#include <cuda_runtime.h>
#include <cstdint>

#define BATCH 2
#define MPTS  5000
#define CH    128
#define KSPP  50
#define NSAMP 2000
#define KNN   1000
#define EPSF  1e-8f

// 80 MB scratch for one branch's d2-partial (bb[m] - 2*dot), reused across branches.
__device__ __align__(16) float g_d2[(size_t)BATCH * NSAMP * MPTS];
// squared norms of feat rows: [branch][b][m]
__device__ __align__(16) float g_bb[2 * BATCH * MPTS];
// accumulators: 0=dist sim sum, 1=ortho sse, 2=bij sse, 3=res sse
__device__ float g_acc[4];

// ---------- packed f32x2 helpers (Blackwell FFMA2) ----------
__device__ __forceinline__ unsigned long long pack2(float x, float y) {
    unsigned long long r;
    asm("mov.b64 %0, {%1, %2};" : "=l"(r) : "f"(x), "f"(y));
    return r;
}
__device__ __forceinline__ void fma2(unsigned long long& d, unsigned long long a,
                                     unsigned long long b) {
    asm("fma.rn.f32x2 %0, %1, %2, %0;" : "+l"(d) : "l"(a), "l"(b));
}
__device__ __forceinline__ void unpack2(unsigned long long v, float& lo, float& hi) {
    asm("mov.b64 {%0, %1}, %2;" : "=f"(lo), "=f"(hi) : "l"(v));
}

__device__ __forceinline__ float warp_sum(float v) {
    #pragma unroll
    for (int o = 16; o; o >>= 1) v += __shfl_xor_sync(0xffffffffu, v, o);
    return v;
}
__device__ __forceinline__ float warp_min(float v) {
    #pragma unroll
    for (int o = 16; o; o >>= 1) v = fminf(v, __shfl_xor_sync(0xffffffffu, v, o));
    return v;
}
__device__ __forceinline__ float warp_max(float v) {
    #pragma unroll
    for (int o = 16; o; o >>= 1) v = fmaxf(v, __shfl_xor_sync(0xffffffffu, v, o));
    return v;
}

// ---------- kernel 1: row norms for both feats + zero accumulators ----------
__global__ void init_norms(const float* __restrict__ f1, const float* __restrict__ f2) {
    if (blockIdx.x == 0 && threadIdx.x < 4) g_acc[threadIdx.x] = 0.f;
    int w = blockIdx.x * 8 + (threadIdx.x >> 5);
    int lane = threadIdx.x & 31;
    if (w >= 2 * BATCH * MPTS) return;
    int branch = w / (BATCH * MPTS);
    int bm = w % (BATCH * MPTS);
    const float* f = (branch ? f2 : f1) + (size_t)bm * CH + lane * 4;
    float4 v = *reinterpret_cast<const float4*>(f);
    float ss = v.x * v.x + v.y * v.y + v.z * v.z + v.w * v.w;
    ss = warp_sum(ss);
    if (lane == 0) g_bb[branch * (BATCH * MPTS) + bm] = ss;
}

// ---------- kernel 2: d2-partial GEMM: g_d2[b][n][m] = bb[m] - 2 * <f1[n], feat[m]> ----------
// 128x128 tile, K=128, BK=8, 256 threads, 8x8 per thread via fma.rn.f32x2 (FFMA2).
// Double-buffered smem: one barrier per k-step, prefetch overlapped with compute.
__global__ __launch_bounds__(256, 2) void gemm_d2(const float* __restrict__ feat,
                                                  const int* __restrict__ ridx,
                                                  int branch) {
    __shared__ __align__(16) float As[2][8][128];
    __shared__ __align__(16) float Bs[2][8][128];
    int tid = threadIdx.x;
    int bx = blockIdx.x, by = blockIdx.y, bz = blockIdx.z;
    const float* fb = feat + (size_t)bz * MPTS * CH;
    const float* bbp = g_bb + branch * (BATCH * MPTS) + bz * MPTS;

    int lrow = tid >> 1;
    int lk4  = (tid & 1) * 4;
    int an = by * 128 + lrow;
    bool aval = an < NSAMP;
    const float* aptr = fb + (size_t)(aval ? ridx[an] : 0) * CH + lk4;
    int bm = bx * 128 + lrow;
    bool bval = bm < MPTS;
    const float* bptr = fb + (size_t)(bval ? bm : 0) * CH + lk4;

    int tx = tid & 15, ty = tid >> 4;
    int tx4 = tx * 4, ty4 = ty * 4;

    unsigned long long acc[8][4];
    #pragma unroll
    for (int i = 0; i < 8; i++)
        #pragma unroll
        for (int j = 0; j < 4; j++) acc[i][j] = 0ull;

    {
        float4 av = aval ? *reinterpret_cast<const float4*>(aptr)
                         : make_float4(0.f, 0.f, 0.f, 0.f);
        float4 bv = bval ? *reinterpret_cast<const float4*>(bptr)
                         : make_float4(0.f, 0.f, 0.f, 0.f);
        As[0][lk4 + 0][lrow] = av.x; As[0][lk4 + 1][lrow] = av.y;
        As[0][lk4 + 2][lrow] = av.z; As[0][lk4 + 3][lrow] = av.w;
        Bs[0][lk4 + 0][lrow] = bv.x; Bs[0][lk4 + 1][lrow] = bv.y;
        Bs[0][lk4 + 2][lrow] = bv.z; Bs[0][lk4 + 3][lrow] = bv.w;
    }
    __syncthreads();

    #pragma unroll 2
    for (int kb = 0; kb < 16; ++kb) {
        int buf = kb & 1;
        float4 av2, bv2;
        if (kb < 15) {
            av2 = aval ? *reinterpret_cast<const float4*>(aptr + (kb + 1) * 8)
                       : make_float4(0.f, 0.f, 0.f, 0.f);
            bv2 = bval ? *reinterpret_cast<const float4*>(bptr + (kb + 1) * 8)
                       : make_float4(0.f, 0.f, 0.f, 0.f);
        }
        #pragma unroll
        for (int kk = 0; kk < 8; kk++) {
            float4 a0 = *reinterpret_cast<const float4*>(&As[buf][kk][ty4]);
            float4 a1 = *reinterpret_cast<const float4*>(&As[buf][kk][64 + ty4]);
            float4 b0 = *reinterpret_cast<const float4*>(&Bs[buf][kk][tx4]);
            float4 b1 = *reinterpret_cast<const float4*>(&Bs[buf][kk][64 + tx4]);
            unsigned long long bp[4] = {pack2(b0.x, b0.y), pack2(b0.z, b0.w),
                                        pack2(b1.x, b1.y), pack2(b1.z, b1.w)};
            float ar[8] = {a0.x, a0.y, a0.z, a0.w, a1.x, a1.y, a1.z, a1.w};
            #pragma unroll
            for (int i = 0; i < 8; i++) {
                unsigned long long ad = pack2(ar[i], ar[i]);
                #pragma unroll
                for (int j = 0; j < 4; j++) fma2(acc[i][j], ad, bp[j]);
            }
        }
        if (kb < 15) {
            int nb = buf ^ 1;
            As[nb][lk4 + 0][lrow] = av2.x; As[nb][lk4 + 1][lrow] = av2.y;
            As[nb][lk4 + 2][lrow] = av2.z; As[nb][lk4 + 3][lrow] = av2.w;
            Bs[nb][lk4 + 0][lrow] = bv2.x; Bs[nb][lk4 + 1][lrow] = bv2.y;
            Bs[nb][lk4 + 2][lrow] = bv2.z; Bs[nb][lk4 + 3][lrow] = bv2.w;
            __syncthreads();
        }
    }

    int n0 = by * 128 + ty4;
    int m0 = bx * 128 + tx4;
    int m1 = m0 + 64;
    float4 bb0 = make_float4(0.f, 0.f, 0.f, 0.f), bb1 = bb0;
    if (m0 < MPTS) bb0 = *reinterpret_cast<const float4*>(bbp + m0);
    if (m1 < MPTS) bb1 = *reinterpret_cast<const float4*>(bbp + m1);
    #pragma unroll
    for (int i = 0; i < 8; i++) {
        int n = (i < 4) ? (n0 + i) : (n0 + 64 + i - 4);
        if (n >= NSAMP) continue;
        float* orow = g_d2 + ((size_t)bz * NSAMP + n) * MPTS;
        float d[8];
        #pragma unroll
        for (int j = 0; j < 4; j++) { unpack2(acc[i][j], d[j * 2], d[j * 2 + 1]); }
        if (m0 < MPTS) {
            float4 o;
            o.x = fmaf(-2.f, d[0], bb0.x); o.y = fmaf(-2.f, d[1], bb0.y);
            o.z = fmaf(-2.f, d[2], bb0.z); o.w = fmaf(-2.f, d[3], bb0.w);
            *reinterpret_cast<float4*>(orow + m0) = o;
        }
        if (m1 < MPTS) {
            float4 o;
            o.x = fmaf(-2.f, d[4], bb1.x); o.y = fmaf(-2.f, d[5], bb1.y);
            o.z = fmaf(-2.f, d[6], bb1.z); o.w = fmaf(-2.f, d[7], bb1.w);
            *reinterpret_cast<float4*>(orow + m1) = o;
        }
    }
}

// ---------- kernel 3: per-row exact k=1000 select + cosine reduction ----------
// Keys are normalized to 24-bit uniform integers u = (k-min)*scale (monotone map),
// so radix bins are uniformly occupied -> naive smem atomics run at spread-address
// rate (no same-bank serialization), and only 3 passes are needed.
__device__ __forceinline__ unsigned int ukey(unsigned int kbits, float mn, float scale) {
    float f = (__uint_as_float(kbits) - mn) * scale;
    unsigned int u = __float2uint_rz(f);
    return u > 0xFFFFFFu ? 0xFFFFFFu : u;
}

__global__ __launch_bounds__(256) void select_reduce(const float* __restrict__ dist,
                                                     const int* __restrict__ ridx,
                                                     int branch) {
    __shared__ __align__(16) unsigned int keys[MPTS];
    __shared__ unsigned int hist[256];
    __shared__ float wred[16];
    __shared__ float sh_mn, sh_scale;
    __shared__ unsigned int sh_P;
    __shared__ int sh_r;
    __shared__ int sh_eq;
    __shared__ float red[96];

    int tid = threadIdx.x;
    int lane = tid & 31;
    int w = tid >> 5;
    int b = blockIdx.x / NSAMP;
    int n = blockIdx.x % NSAMP;
    int col = ridx[n];
    float aa = g_bb[branch * (BATCH * MPTS) + b * MPTS + col];
    const float* rowp = g_d2 + (size_t)blockIdx.x * MPTS;

    // load row, add aa, clamp >= 0; track min/max
    float lmn = 3.4e38f, lmx = 0.f;
    for (int q = tid; q < MPTS / 4; q += 256) {
        float4 v = reinterpret_cast<const float4*>(rowp)[q];
        float x0 = fmaxf(v.x + aa, 0.f), x1 = fmaxf(v.y + aa, 0.f);
        float x2 = fmaxf(v.z + aa, 0.f), x3 = fmaxf(v.w + aa, 0.f);
        uint4 k;
        k.x = __float_as_uint(x0); k.y = __float_as_uint(x1);
        k.z = __float_as_uint(x2); k.w = __float_as_uint(x3);
        reinterpret_cast<uint4*>(keys)[q] = k;
        lmn = fminf(lmn, fminf(fminf(x0, x1), fminf(x2, x3)));
        lmx = fmaxf(lmx, fmaxf(fmaxf(x0, x1), fmaxf(x2, x3)));
    }
    lmn = warp_min(lmn);
    lmx = warp_max(lmx);
    if (lane == 0) { wred[w] = lmn; wred[8 + w] = lmx; }
    if (tid == 0) { sh_P = 0; sh_r = KNN; sh_eq = 0; }
    __syncthreads();
    if (tid == 0) {
        float mn = wred[0], mx = wred[8];
        #pragma unroll
        for (int i = 1; i < 8; i++) { mn = fminf(mn, wred[i]); mx = fmaxf(mx, wred[8 + i]); }
        sh_mn = mn;
        sh_scale = 16777215.0f / fmaxf(mx - mn, 1e-30f);
    }
    __syncthreads();
    float mn = sh_mn, scale = sh_scale;

    // 3-pass MSD radix select on 24-bit normalized keys
    #pragma unroll
    for (int pass = 0; pass < 3; ++pass) {
        int shift = 16 - 8 * pass;
        unsigned int P = sh_P;
        unsigned int pmask = (pass == 0) ? 0u
                           : (pass == 1) ? 0xFF0000u : 0xFFFF00u;
        hist[tid] = 0;
        __syncthreads();
        for (int i = tid; i < MPTS; i += 256) {
            unsigned int u = ukey(keys[i], mn, scale);
            if ((u & pmask) == P) atomicAdd(&hist[(u >> shift) & 255], 1u);
        }
        __syncthreads();
        // warp 0: parallel cumsum over 256 bins (8 per lane) + bin find
        if (tid < 32) {
            unsigned int c[8];
            unsigned int s = 0;
            int base = tid * 8;
            #pragma unroll
            for (int j = 0; j < 8; j++) { c[j] = hist[base + j]; s += c[j]; }
            unsigned int inc = s;
            #pragma unroll
            for (int o = 1; o < 32; o <<= 1) {
                unsigned int v = __shfl_up_sync(0xffffffffu, inc, o);
                if (tid >= o) inc += v;
            }
            unsigned int excl = inc - s;
            unsigned int r = (unsigned int)sh_r;
            if (r > excl && r <= inc) {   // exactly one lane qualifies
                unsigned int cum = excl;
                #pragma unroll
                for (int j = 0; j < 8; j++) {
                    if (cum + c[j] >= r) {
                        sh_P = P | ((unsigned int)(base + j) << shift);
                        sh_r = (int)(r - cum);
                        break;
                    }
                    cum += c[j];
                }
            }
        }
        __syncthreads();
    }
    unsigned int T = sh_P;   // normalized key of the 1000th smallest
    int need_eq = sh_r;      // ties at T to include

    const float* dcol = dist + (size_t)b * MPTS * MPTS + col;
    float num = 0.f, s1 = 0.f, s2 = 0.f;
    for (int i = tid; i < MPTS; i += 256) {
        unsigned int kb = keys[i];
        unsigned int u = ukey(kb, mn, scale);
        bool take = (u < T);
        if (!take && u == T) take = (atomicAdd(&sh_eq, 1) < need_eq);
        if (take) {
            float dr = sqrtf(fmaxf(__uint_as_float(kb), 1e-12f));
            float df = __ldg(dcol + (size_t)i * MPTS);
            num = fmaf(dr, df, num);
            s1  = fmaf(dr, dr, s1);
            s2  = fmaf(df, df, s2);
        }
    }
    num = warp_sum(num); s1 = warp_sum(s1); s2 = warp_sum(s2);
    if (lane == 0) { red[w] = num; red[32 + w] = s1; red[64 + w] = s2; }
    __syncthreads();
    if (tid == 0) {
        float N = 0.f, S1 = 0.f, S2 = 0.f;
        #pragma unroll
        for (int i = 0; i < 8; i++) { N += red[i]; S1 += red[32 + i]; S2 += red[64 + i]; }
        float den = fmaxf(sqrtf(S1), EPSF) * fmaxf(sqrtf(S2), EPSF);
        float sim = 1.f - fabsf(N / den);
        atomicAdd(&g_acc[0], sim);
    }
}

// ---------- kernel 4: ortho / bij / res losses on the 50x50 matrices ----------
__global__ void small_losses(const float* __restrict__ A0, const float* __restrict__ A1,
                             const float* __restrict__ A2, const float* __restrict__ A3) {
    __shared__ float shA[KSPP * KSPP];
    __shared__ float shB[KSPP * KSPP];
    __shared__ float red[8];
    int t = blockIdx.x, b = blockIdx.y, tid = threadIdx.x;
    const float* mats[4] = {A0, A1, A2, A3};
    size_t off = (size_t)b * KSPP * KSPP;
    float local = 0.f;
    if (t == 6) {
        for (int e = tid; e < KSPP * KSPP; e += 256) {
            float d1 = A0[off + e] - A2[off + e];
            float d2 = A1[off + e] - A3[off + e];
            local += d1 * d1 + d2 * d2;
        }
    } else {
        int ai, bi; bool tb;
        switch (t) {
            case 0: ai = 0; bi = 0; tb = true;  break;
            case 1: ai = 1; bi = 1; tb = true;  break;
            case 2: ai = 2; bi = 2; tb = true;  break;
            case 3: ai = 3; bi = 3; tb = true;  break;
            case 4: ai = 0; bi = 1; tb = false; break;
            default: ai = 1; bi = 0; tb = false; break;
        }
        for (int e = tid; e < KSPP * KSPP; e += 256) {
            shA[e] = mats[ai][off + e];
            shB[e] = mats[bi][off + e];
        }
        __syncthreads();
        for (int e = tid; e < KSPP * KSPP; e += 256) {
            int i = e / KSPP, j = e % KSPP;
            float dot = 0.f;
            if (tb) {
                for (int k = 0; k < KSPP; k++) dot = fmaf(shA[i * KSPP + k], shB[j * KSPP + k], dot);
            } else {
                for (int k = 0; k < KSPP; k++) dot = fmaf(shA[i * KSPP + k], shB[k * KSPP + j], dot);
            }
            float diff = dot - (i == j ? 1.f : 0.f);
            local += diff * diff;
        }
    }
    local = warp_sum(local);
    if ((tid & 31) == 0) red[tid >> 5] = local;
    __syncthreads();
    if (tid == 0) {
        float s = 0.f;
        #pragma unroll
        for (int i = 0; i < 8; i++) s += red[i];
        int slot = (t < 4) ? 1 : ((t < 6) ? 2 : 3);
        atomicAdd(&g_acc[slot], s);
    }
}

// ---------- kernel 5: combine ----------
__global__ void finalize(float* __restrict__ out) {
    float dist  = g_acc[0] * 0.5f;
    float ortho = g_acc[1] / (float)BATCH * 0.5f;
    float bij   = g_acc[2] / (float)BATCH;
    float res   = g_acc[3] / (float)BATCH;
    out[0] = dist + ortho + bij + res;
    out[1] = ortho;
    out[2] = bij;
    out[3] = res;
    out[4] = dist;
}

extern "C" void kernel_launch(void* const* d_in, const int* in_sizes, int n_in,
                              void* d_out, int out_size) {
    const float* C12   = (const float*)d_in[0];
    const float* C21   = (const float*)d_in[1];
    const float* C12n  = (const float*)d_in[2];
    const float* C21n  = (const float*)d_in[3];
    const float* feat1 = (const float*)d_in[4];
    const float* feat2 = (const float*)d_in[5];
    const float* dist1 = (const float*)d_in[8];
    const float* dist2 = (const float*)d_in[9];
    const int*   ri1   = (const int*)d_in[10];
    const int*   ri2   = (const int*)d_in[11];
    float* out = (float*)d_out;

    init_norms<<<2500, 256>>>(feat1, feat2);

    dim3 ggrid((MPTS + 127) / 128, (NSAMP + 127) / 128, BATCH);  // 40 x 16 x 2
    gemm_d2<<<ggrid, 256>>>(feat1, ri1, 0);
    select_reduce<<<BATCH * NSAMP, 256>>>(dist1, ri1, 0);
    gemm_d2<<<ggrid, 256>>>(feat2, ri2, 1);
    select_reduce<<<BATCH * NSAMP, 256>>>(dist2, ri2, 1);

    small_losses<<<dim3(7, BATCH), 256>>>(C12, C21, C12n, C21n);
    finalize<<<1, 1>>>(out);
}

// round 5
// speedup vs baseline: 1.4679x; 1.0532x over previous
#include <cuda_runtime.h>
#include <cuda_bf16.h>
#include <cstdint>

#define BATCH 2
#define MPTS  5000
#define CH    128
#define KSPP  50
#define NSAMP 2000
#define KNN   1000
#define EPSF  1e-8f

// 80 MB scratch for one branch's d2 partial (bb[m] - 2*dot), reused across branches.
__device__ __align__(16) float g_d2[(size_t)BATCH * NSAMP * MPTS];
// squared norms of feat rows: [branch][b][m]
__device__ __align__(16) float g_bb[2 * BATCH * MPTS];
// accumulators: 0=dist sim sum, 1=ortho sse, 2=bij sse, 3=res sse
__device__ float g_acc[4];

// ===================== helpers =====================
__device__ __forceinline__ float warp_sum(float v) {
    #pragma unroll
    for (int o = 16; o; o >>= 1) v += __shfl_xor_sync(0xffffffffu, v, o);
    return v;
}
__device__ __forceinline__ float warp_min(float v) {
    #pragma unroll
    for (int o = 16; o; o >>= 1) v = fminf(v, __shfl_xor_sync(0xffffffffu, v, o));
    return v;
}
__device__ __forceinline__ float warp_max(float v) {
    #pragma unroll
    for (int o = 16; o; o >>= 1) v = fmaxf(v, __shfl_xor_sync(0xffffffffu, v, o));
    return v;
}

// m16n8k16 row.col bf16 MMA, fp32 accumulate (legacy HMMA path, valid on sm_103)
__device__ __forceinline__ void mma_bf16(float* c, const uint32_t* a, const uint32_t* b) {
    asm volatile(
        "mma.sync.aligned.m16n8k16.row.col.f32.bf16.bf16.f32 "
        "{%0,%1,%2,%3}, {%4,%5,%6,%7}, {%8,%9}, {%0,%1,%2,%3};"
        : "+f"(c[0]), "+f"(c[1]), "+f"(c[2]), "+f"(c[3])
        : "r"(a[0]), "r"(a[1]), "r"(a[2]), "r"(a[3]), "r"(b[0]), "r"(b[1]));
}

// ---------- kernel 1: row norms for both feats + zero accumulators ----------
__global__ void init_norms(const float* __restrict__ f1, const float* __restrict__ f2) {
    if (blockIdx.x == 0 && threadIdx.x < 4) g_acc[threadIdx.x] = 0.f;
    int w = blockIdx.x * 8 + (threadIdx.x >> 5);
    int lane = threadIdx.x & 31;
    if (w >= 2 * BATCH * MPTS) return;
    int branch = w / (BATCH * MPTS);
    int bm = w % (BATCH * MPTS);
    const float* f = (branch ? f2 : f1) + (size_t)bm * CH + lane * 4;
    float4 v = *reinterpret_cast<const float4*>(f);
    float ss = v.x * v.x + v.y * v.y + v.z * v.z + v.w * v.w;
    ss = warp_sum(ss);
    if (lane == 0) g_bb[branch * (BATCH * MPTS) + bm] = ss;
}

// ===================== kernel 2: HMMA GEMM for d2 partial =====================
// Tile 128 samples x 128 points x K=128. fp32 -> bf16 hi/lo split:
// dot = Ah*Bh + Ah*Bl + Al*Bh (fp32 accum). g_d2[b][n][m] = bb[m] - 2*dot.
// Smem: 4 matrices [128][SPAD] bf16, SPAD=136 -> conflict-free frag loads.
#define SPAD 136
#define U32_PER_MAT (128 * SPAD / 2)      // 8704 u32 per matrix
#define SMEM_MMA_BYTES (4 * U32_PER_MAT * 4)   // 139264

// fp32x4 -> hi/lo bf16x2 pairs
__device__ __forceinline__ void cvt_hilo(float4 v, uint32_t& h01, uint32_t& h23,
                                         uint32_t& l01, uint32_t& l23) {
    asm("cvt.rn.bf16x2.f32 %0, %1, %2;" : "=r"(h01) : "f"(v.y), "f"(v.x));
    asm("cvt.rn.bf16x2.f32 %0, %1, %2;" : "=r"(h23) : "f"(v.w), "f"(v.z));
    float r0 = v.x - __uint_as_float(h01 << 16);
    float r1 = v.y - __uint_as_float(h01 & 0xffff0000u);
    float r2 = v.z - __uint_as_float(h23 << 16);
    float r3 = v.w - __uint_as_float(h23 & 0xffff0000u);
    asm("cvt.rn.bf16x2.f32 %0, %1, %2;" : "=r"(l01) : "f"(r1), "f"(r0));
    asm("cvt.rn.bf16x2.f32 %0, %1, %2;" : "=r"(l23) : "f"(r3), "f"(r2));
}

__global__ __launch_bounds__(256, 1) void gemm_mma(const float* __restrict__ feat,
                                                   const int* __restrict__ ridx,
                                                   int branch) {
    extern __shared__ __align__(16) char smraw[];
    uint32_t* AH = reinterpret_cast<uint32_t*>(smraw);
    uint32_t* AL = AH + U32_PER_MAT;
    uint32_t* BH = AL + U32_PER_MAT;
    uint32_t* BL = BH + U32_PER_MAT;

    int tid = threadIdx.x;
    int bx = blockIdx.x;   // point tile (128)
    int by = blockIdx.y;   // sample tile (128)
    int bz = blockIdx.z;
    const float* fb = feat + (size_t)bz * MPTS * CH;

    // ---- load + convert A (gathered samples) and B (points), 128 rows x 128 fp32 each ----
    #pragma unroll 4
    for (int it = 0; it < 16; ++it) {
        int idx = it * 256 + tid;
        int r = idx >> 5, c16 = idx & 31;          // c16: float4 index within row
        int gi = by * 128 + r; if (gi >= NSAMP) gi = NSAMP - 1;
        float4 v = *reinterpret_cast<const float4*>(fb + (size_t)ridx[gi] * CH + c16 * 4);
        uint32_t h01, h23, l01, l23;
        cvt_hilo(v, h01, h23, l01, l23);
        int o = r * (SPAD / 2) + c16 * 2;
        AH[o] = h01; AH[o + 1] = h23;
        AL[o] = l01; AL[o + 1] = l23;
    }
    #pragma unroll 4
    for (int it = 0; it < 16; ++it) {
        int idx = it * 256 + tid;
        int r = idx >> 5, c16 = idx & 31;
        int gm = bx * 128 + r; if (gm >= MPTS) gm = MPTS - 1;
        float4 v = *reinterpret_cast<const float4*>(fb + (size_t)gm * CH + c16 * 4);
        uint32_t h01, h23, l01, l23;
        cvt_hilo(v, h01, h23, l01, l23);
        int o = r * (SPAD / 2) + c16 * 2;
        BH[o] = h01; BH[o + 1] = h23;
        BL[o] = l01; BL[o + 1] = l23;
    }
    __syncthreads();

    // ---- warp tiling: 8 warps = 2 (m) x 4 (n); each warp 64x32 = 4x4 mma tiles ----
    int wid = tid >> 5, lane = tid & 31;
    int g = lane >> 2, tig = lane & 3;
    int wm = (wid >> 2) * 64;
    int wn = (wid & 3) * 32;

    float acc[4][4][4];
    #pragma unroll
    for (int i = 0; i < 4; i++)
        #pragma unroll
        for (int j = 0; j < 4; j++)
            #pragma unroll
            for (int q = 0; q < 4; q++) acc[i][j][q] = 0.f;

    #pragma unroll
    for (int ks = 0; ks < 8; ++ks) {
        int k0 = ks * 16;
        uint32_t ah[4][4], al[4][4], bh[4][2], bl[4][2];
        #pragma unroll
        for (int mt = 0; mt < 4; ++mt) {
            int e = (wm + mt * 16 + g) * SPAD + k0 + tig * 2;
            int o = e >> 1;
            int o8 = o + 4 * SPAD;                 // row + 8
            ah[mt][0] = AH[o];     ah[mt][1] = AH[o8];
            ah[mt][2] = AH[o + 4]; ah[mt][3] = AH[o8 + 4];   // col + 8
            al[mt][0] = AL[o];     al[mt][1] = AL[o8];
            al[mt][2] = AL[o + 4]; al[mt][3] = AL[o8 + 4];
        }
        #pragma unroll
        for (int nt = 0; nt < 4; ++nt) {
            int e = (wn + nt * 8 + g) * SPAD + k0 + tig * 2;
            int o = e >> 1;
            bh[nt][0] = BH[o]; bh[nt][1] = BH[o + 4];
            bl[nt][0] = BL[o]; bl[nt][1] = BL[o + 4];
        }
        #pragma unroll
        for (int mt = 0; mt < 4; ++mt)
            #pragma unroll
            for (int nt = 0; nt < 4; ++nt) {
                mma_bf16(acc[mt][nt], ah[mt], bh[nt]);
                mma_bf16(acc[mt][nt], ah[mt], bl[nt]);
                mma_bf16(acc[mt][nt], al[mt], bh[nt]);
            }
    }

    // ---- epilogue: d2 = bb[m] - 2*dot, float2 stores ----
    const float* bbp = g_bb + branch * (BATCH * MPTS) + bz * MPTS;
    #pragma unroll
    for (int mt = 0; mt < 4; ++mt) {
        #pragma unroll
        for (int half = 0; half < 2; ++half) {
            int ns = by * 128 + wm + mt * 16 + g + half * 8;
            if (ns >= NSAMP) continue;
            float* orow = g_d2 + ((size_t)bz * NSAMP + ns) * MPTS;
            #pragma unroll
            for (int nt = 0; nt < 4; ++nt) {
                int mp = bx * 128 + wn + nt * 8 + tig * 2;
                if (mp < MPTS) {
                    float2 bbv = *reinterpret_cast<const float2*>(bbp + mp);
                    float2 o;
                    o.x = fmaf(-2.f, acc[mt][nt][half * 2 + 0], bbv.x);
                    o.y = fmaf(-2.f, acc[mt][nt][half * 2 + 1], bbv.y);
                    *reinterpret_cast<float2*>(orow + mp) = o;
                }
            }
        }
    }
}

// ---------- kernel 3: per-row exact k=1000 select + cosine reduction ----------
// Single-pass 12-bit histogram select: keys normalized to [0,4095] (monotone),
// one histogram sweep + block scan; exact KNN count via tie atomics at threshold bin.
__device__ __forceinline__ unsigned int ukey12(unsigned int kbits, float mn, float scale) {
    float f = (__uint_as_float(kbits) - mn) * scale;
    unsigned int u = __float2uint_rz(f);
    return u > 4095u ? 4095u : u;
}

__global__ __launch_bounds__(256) void select_reduce(const float* __restrict__ dist,
                                                     const int* __restrict__ ridx,
                                                     int branch) {
    __shared__ __align__(16) unsigned int keys[MPTS];
    __shared__ unsigned int hist[4096];
    __shared__ float wred[16];
    __shared__ float sh_mn, sh_scale;
    __shared__ unsigned int wtot[8];
    __shared__ unsigned int sh_T;
    __shared__ int sh_r;
    __shared__ int sh_eq;
    __shared__ float red[96];

    int tid = threadIdx.x;
    int lane = tid & 31;
    int w = tid >> 5;
    int b = blockIdx.x / NSAMP;
    int n = blockIdx.x % NSAMP;
    int col = ridx[n];
    float aa = g_bb[branch * (BATCH * MPTS) + b * MPTS + col];
    const float* rowp = g_d2 + (size_t)blockIdx.x * MPTS;

    // load row, add aa, clamp >= 0; track min/max; zero histogram
    for (int j = tid; j < 4096; j += 256) hist[j] = 0;
    float lmn = 3.4e38f, lmx = 0.f;
    for (int q = tid; q < MPTS / 4; q += 256) {
        float4 v = reinterpret_cast<const float4*>(rowp)[q];
        float x0 = fmaxf(v.x + aa, 0.f), x1 = fmaxf(v.y + aa, 0.f);
        float x2 = fmaxf(v.z + aa, 0.f), x3 = fmaxf(v.w + aa, 0.f);
        uint4 k;
        k.x = __float_as_uint(x0); k.y = __float_as_uint(x1);
        k.z = __float_as_uint(x2); k.w = __float_as_uint(x3);
        reinterpret_cast<uint4*>(keys)[q] = k;
        lmn = fminf(lmn, fminf(fminf(x0, x1), fminf(x2, x3)));
        lmx = fmaxf(lmx, fmaxf(fmaxf(x0, x1), fmaxf(x2, x3)));
    }
    lmn = warp_min(lmn);
    lmx = warp_max(lmx);
    if (lane == 0) { wred[w] = lmn; wred[8 + w] = lmx; }
    if (tid == 0) sh_eq = 0;
    __syncthreads();
    if (tid == 0) {
        float mn = wred[0], mx = wred[8];
        #pragma unroll
        for (int i = 1; i < 8; i++) { mn = fminf(mn, wred[i]); mx = fmaxf(mx, wred[8 + i]); }
        sh_mn = mn;
        sh_scale = 4095.0f / fmaxf(mx - mn, 1e-30f);
    }
    __syncthreads();
    float mn = sh_mn, scale = sh_scale;

    // single histogram pass (bins ~uniform: ~1.2 keys/bin)
    for (int i = tid; i < MPTS; i += 256)
        atomicAdd(&hist[ukey12(keys[i], mn, scale)], 1u);
    __syncthreads();

    // block scan over 4096 bins (16 per thread) to locate the KNN-th bin
    {
        unsigned int c[16];
        unsigned int s = 0;
        int base = tid * 16;
        #pragma unroll
        for (int j = 0; j < 16; j++) { c[j] = hist[base + j]; s += c[j]; }
        unsigned int inc = s;
        #pragma unroll
        for (int o = 1; o < 32; o <<= 1) {
            unsigned int v = __shfl_up_sync(0xffffffffu, inc, o);
            if (lane >= o) inc += v;
        }
        if (lane == 31) wtot[w] = inc;
        __syncthreads();
        if (tid == 0) {
            unsigned int t = 0;
            #pragma unroll
            for (int i = 0; i < 8; i++) { unsigned int v = wtot[i]; wtot[i] = t; t += v; }
        }
        __syncthreads();
        unsigned int excl = wtot[w] + inc - s;
        if (KNN > excl && KNN <= excl + s) {     // exactly one thread
            unsigned int cum = excl;
            #pragma unroll
            for (int j = 0; j < 16; j++) {
                if (cum + c[j] >= KNN) { sh_T = (unsigned int)(base + j); sh_r = (int)(KNN - cum); break; }
                cum += c[j];
            }
        }
    }
    __syncthreads();
    unsigned int T = sh_T;
    int need_eq = sh_r;

    const float* dcol = dist + (size_t)b * MPTS * MPTS + col;
    float num = 0.f, s1 = 0.f, s2 = 0.f;
    for (int i = tid; i < MPTS; i += 256) {
        unsigned int kb = keys[i];
        unsigned int u = ukey12(kb, mn, scale);
        bool take = (u < T);
        if (!take && u == T) take = (atomicAdd(&sh_eq, 1) < need_eq);
        if (take) {
            float dr = sqrtf(fmaxf(__uint_as_float(kb), 1e-12f));
            float df = __ldg(dcol + (size_t)i * MPTS);
            num = fmaf(dr, df, num);
            s1  = fmaf(dr, dr, s1);
            s2  = fmaf(df, df, s2);
        }
    }
    num = warp_sum(num); s1 = warp_sum(s1); s2 = warp_sum(s2);
    if (lane == 0) { red[w] = num; red[32 + w] = s1; red[64 + w] = s2; }
    __syncthreads();
    if (tid == 0) {
        float N = 0.f, S1 = 0.f, S2 = 0.f;
        #pragma unroll
        for (int i = 0; i < 8; i++) { N += red[i]; S1 += red[32 + i]; S2 += red[64 + i]; }
        float den = fmaxf(sqrtf(S1), EPSF) * fmaxf(sqrtf(S2), EPSF);
        float sim = 1.f - fabsf(N / den);
        atomicAdd(&g_acc[0], sim);
    }
}

// ---------- kernel 4: ortho / bij / res losses on the 50x50 matrices ----------
__global__ void small_losses(const float* __restrict__ A0, const float* __restrict__ A1,
                             const float* __restrict__ A2, const float* __restrict__ A3) {
    __shared__ float shA[KSPP * KSPP];
    __shared__ float shB[KSPP * KSPP];
    __shared__ float red[8];
    int t = blockIdx.x, b = blockIdx.y, tid = threadIdx.x;
    const float* mats[4] = {A0, A1, A2, A3};
    size_t off = (size_t)b * KSPP * KSPP;
    float local = 0.f;
    if (t == 6) {
        for (int e = tid; e < KSPP * KSPP; e += 256) {
            float d1 = A0[off + e] - A2[off + e];
            float d2 = A1[off + e] - A3[off + e];
            local += d1 * d1 + d2 * d2;
        }
    } else {
        int ai, bi; bool tb;
        switch (t) {
            case 0: ai = 0; bi = 0; tb = true;  break;
            case 1: ai = 1; bi = 1; tb = true;  break;
            case 2: ai = 2; bi = 2; tb = true;  break;
            case 3: ai = 3; bi = 3; tb = true;  break;
            case 4: ai = 0; bi = 1; tb = false; break;
            default: ai = 1; bi = 0; tb = false; break;
        }
        for (int e = tid; e < KSPP * KSPP; e += 256) {
            shA[e] = mats[ai][off + e];
            shB[e] = mats[bi][off + e];
        }
        __syncthreads();
        for (int e = tid; e < KSPP * KSPP; e += 256) {
            int i = e / KSPP, j = e % KSPP;
            float dot = 0.f;
            if (tb) {
                for (int k = 0; k < KSPP; k++) dot = fmaf(shA[i * KSPP + k], shB[j * KSPP + k], dot);
            } else {
                for (int k = 0; k < KSPP; k++) dot = fmaf(shA[i * KSPP + k], shB[k * KSPP + j], dot);
            }
            float diff = dot - (i == j ? 1.f : 0.f);
            local += diff * diff;
        }
    }
    local = warp_sum(local);
    if ((tid & 31) == 0) red[tid >> 5] = local;
    __syncthreads();
    if (tid == 0) {
        float s = 0.f;
        #pragma unroll
        for (int i = 0; i < 8; i++) s += red[i];
        int slot = (t < 4) ? 1 : ((t < 6) ? 2 : 3);
        atomicAdd(&g_acc[slot], s);
    }
}

// ---------- kernel 5: combine ----------
__global__ void finalize(float* __restrict__ out) {
    float dist  = g_acc[0] * 0.5f;
    float ortho = g_acc[1] / (float)BATCH * 0.5f;
    float bij   = g_acc[2] / (float)BATCH;
    float res   = g_acc[3] / (float)BATCH;
    out[0] = dist + ortho + bij + res;
    out[1] = ortho;
    out[2] = bij;
    out[3] = res;
    out[4] = dist;
}

extern "C" void kernel_launch(void* const* d_in, const int* in_sizes, int n_in,
                              void* d_out, int out_size) {
    const float* C12   = (const float*)d_in[0];
    const float* C21   = (const float*)d_in[1];
    const float* C12n  = (const float*)d_in[2];
    const float* C21n  = (const float*)d_in[3];
    const float* feat1 = (const float*)d_in[4];
    const float* feat2 = (const float*)d_in[5];
    const float* dist1 = (const float*)d_in[8];
    const float* dist2 = (const float*)d_in[9];
    const int*   ri1   = (const int*)d_in[10];
    const int*   ri2   = (const int*)d_in[11];
    float* out = (float*)d_out;

    static bool attr_set = false;
    if (!attr_set) {
        cudaFuncSetAttribute(gemm_mma, cudaFuncAttributeMaxDynamicSharedMemorySize,
                             SMEM_MMA_BYTES);
        attr_set = true;
    }

    init_norms<<<2500, 256>>>(feat1, feat2);

    dim3 tg((MPTS + 127) / 128, (NSAMP + 127) / 128, BATCH);   // 40 x 16 x 2
    gemm_mma<<<tg, 256, SMEM_MMA_BYTES>>>(feat1, ri1, 0);
    select_reduce<<<BATCH * NSAMP, 256>>>(dist1, ri1, 0);
    gemm_mma<<<tg, 256, SMEM_MMA_BYTES>>>(feat2, ri2, 1);
    select_reduce<<<BATCH * NSAMP, 256>>>(dist2, ri2, 1);

    small_losses<<<dim3(7, BATCH), 256>>>(C12, C21, C12n, C21n);
    finalize<<<1, 1>>>(out);
}

// round 6
// speedup vs baseline: 1.8298x; 1.2465x over previous
#include <cuda_runtime.h>
#include <cuda_bf16.h>
#include <cstdint>

#define BATCH 2
#define MPTS  5000
#define CH    128
#define KSPP  50
#define NSAMP 2000
#define KNN   1000
#define EPSF  1e-8f

__device__ __align__(16) float g_d2[(size_t)BATCH * NSAMP * MPTS];
__device__ __align__(16) float g_bb[2 * BATCH * MPTS];
__device__ float g_acc[4];

// ===================== helpers =====================
__device__ __forceinline__ float warp_sum(float v) {
    #pragma unroll
    for (int o = 16; o; o >>= 1) v += __shfl_xor_sync(0xffffffffu, v, o);
    return v;
}
__device__ __forceinline__ float warp_min(float v) {
    #pragma unroll
    for (int o = 16; o; o >>= 1) v = fminf(v, __shfl_xor_sync(0xffffffffu, v, o));
    return v;
}
__device__ __forceinline__ float warp_max(float v) {
    #pragma unroll
    for (int o = 16; o; o >>= 1) v = fmaxf(v, __shfl_xor_sync(0xffffffffu, v, o));
    return v;
}

__device__ __forceinline__ void mma_bf16(float* c, const uint32_t* a, const uint32_t* b) {
    asm volatile(
        "mma.sync.aligned.m16n8k16.row.col.f32.bf16.bf16.f32 "
        "{%0,%1,%2,%3}, {%4,%5,%6,%7}, {%8,%9}, {%0,%1,%2,%3};"
        : "+f"(c[0]), "+f"(c[1]), "+f"(c[2]), "+f"(c[3])
        : "r"(a[0]), "r"(a[1]), "r"(a[2]), "r"(a[3]), "r"(b[0]), "r"(b[1]));
}

// ---------- kernel 1: row norms + zero accumulators ----------
__global__ void init_norms(const float* __restrict__ f1, const float* __restrict__ f2) {
    if (blockIdx.x == 0 && threadIdx.x < 4) g_acc[threadIdx.x] = 0.f;
    int w = blockIdx.x * 8 + (threadIdx.x >> 5);
    int lane = threadIdx.x & 31;
    if (w >= 2 * BATCH * MPTS) return;
    int branch = w / (BATCH * MPTS);
    int bm = w % (BATCH * MPTS);
    const float* f = (branch ? f2 : f1) + (size_t)bm * CH + lane * 4;
    float4 v = *reinterpret_cast<const float4*>(f);
    float ss = v.x * v.x + v.y * v.y + v.z * v.z + v.w * v.w;
    ss = warp_sum(ss);
    if (lane == 0) g_bb[branch * (BATCH * MPTS) + bm] = ss;
}

// ===================== kernel 2: HMMA GEMM, K-chunked for occupancy =====================
// Tile 128x128, K in 2 chunks of 64. fp32 -> bf16 hi/lo split:
// dot = Ah*Bh + Ah*Bl + Al*Bh. Smem: 4 matrices [128][72] bf16 = 73728 B -> 2 CTAs/SM.
#define KC 64
#define SPAD 72                              // bf16 elements per padded row
#define ROWU (SPAD / 2)                      // 36 u32 per row
#define U32_PER_MAT (128 * ROWU)             // 4608
#define SMEM_MMA_BYTES (4 * U32_PER_MAT * 4) // 73728

__device__ __forceinline__ void cvt_hilo(float4 v, uint32_t& h01, uint32_t& h23,
                                         uint32_t& l01, uint32_t& l23) {
    asm("cvt.rn.bf16x2.f32 %0, %1, %2;" : "=r"(h01) : "f"(v.y), "f"(v.x));
    asm("cvt.rn.bf16x2.f32 %0, %1, %2;" : "=r"(h23) : "f"(v.w), "f"(v.z));
    float r0 = v.x - __uint_as_float(h01 << 16);
    float r1 = v.y - __uint_as_float(h01 & 0xffff0000u);
    float r2 = v.z - __uint_as_float(h23 << 16);
    float r3 = v.w - __uint_as_float(h23 & 0xffff0000u);
    asm("cvt.rn.bf16x2.f32 %0, %1, %2;" : "=r"(l01) : "f"(r1), "f"(r0));
    asm("cvt.rn.bf16x2.f32 %0, %1, %2;" : "=r"(l23) : "f"(r3), "f"(r2));
}

__global__ __launch_bounds__(256, 2) void gemm_mma(const float* __restrict__ feat,
                                                   const int* __restrict__ ridx,
                                                   int branch) {
    extern __shared__ __align__(16) char smraw[];
    uint32_t* AH = reinterpret_cast<uint32_t*>(smraw);
    uint32_t* AL = AH + U32_PER_MAT;
    uint32_t* BH = AL + U32_PER_MAT;
    uint32_t* BL = BH + U32_PER_MAT;

    int tid = threadIdx.x;
    int bx = blockIdx.x, by = blockIdx.y, bz = blockIdx.z;
    const float* fb = feat + (size_t)bz * MPTS * CH;

    int wid = tid >> 5, lane = tid & 31;
    int g = lane >> 2, tig = lane & 3;
    int wm = (wid >> 2) * 64;
    int wn = (wid & 3) * 32;

    float acc[4][4][4];
    #pragma unroll
    for (int i = 0; i < 4; i++)
        #pragma unroll
        for (int j = 0; j < 4; j++)
            #pragma unroll
            for (int q = 0; q < 4; q++) acc[i][j][q] = 0.f;

    // precompute gathered A row index for this thread's load rows (same rows both chunks)
    #pragma unroll 1
    for (int ck = 0; ck < 2; ++ck) {
        if (ck) __syncthreads();             // previous chunk's compute done
        // load+convert A chunk: 128 rows x 64 floats = 2048 float4; 8 its x 256 thr
        #pragma unroll 2
        for (int it = 0; it < 8; ++it) {
            int idx = it * 256 + tid;
            int r = idx >> 4, c16 = idx & 15;
            int gi = by * 128 + r; if (gi >= NSAMP) gi = NSAMP - 1;
            float4 v = *reinterpret_cast<const float4*>(
                fb + (size_t)ridx[gi] * CH + ck * KC + c16 * 4);
            uint32_t h01, h23, l01, l23;
            cvt_hilo(v, h01, h23, l01, l23);
            int o = r * ROWU + c16 * 2;
            AH[o] = h01; AH[o + 1] = h23;
            AL[o] = l01; AL[o + 1] = l23;
        }
        // load+convert B chunk
        #pragma unroll 2
        for (int it = 0; it < 8; ++it) {
            int idx = it * 256 + tid;
            int r = idx >> 4, c16 = idx & 15;
            int gm = bx * 128 + r; if (gm >= MPTS) gm = MPTS - 1;
            float4 v = *reinterpret_cast<const float4*>(
                fb + (size_t)gm * CH + ck * KC + c16 * 4);
            uint32_t h01, h23, l01, l23;
            cvt_hilo(v, h01, h23, l01, l23);
            int o = r * ROWU + c16 * 2;
            BH[o] = h01; BH[o + 1] = h23;
            BL[o] = l01; BL[o + 1] = l23;
        }
        __syncthreads();

        #pragma unroll
        for (int ks = 0; ks < 4; ++ks) {
            int k0 = ks * 16;
            uint32_t ah[4][4], al[4][4], bh[4][2], bl[4][2];
            #pragma unroll
            for (int mt = 0; mt < 4; ++mt) {
                int o = (wm + mt * 16 + g) * ROWU + (k0 >> 1) + tig;
                int o8 = o + 8 * ROWU;
                ah[mt][0] = AH[o];     ah[mt][1] = AH[o8];
                ah[mt][2] = AH[o + 4]; ah[mt][3] = AH[o8 + 4];
                al[mt][0] = AL[o];     al[mt][1] = AL[o8];
                al[mt][2] = AL[o + 4]; al[mt][3] = AL[o8 + 4];
            }
            #pragma unroll
            for (int nt = 0; nt < 4; ++nt) {
                int o = (wn + nt * 8 + g) * ROWU + (k0 >> 1) + tig;
                bh[nt][0] = BH[o]; bh[nt][1] = BH[o + 4];
                bl[nt][0] = BL[o]; bl[nt][1] = BL[o + 4];
            }
            #pragma unroll
            for (int mt = 0; mt < 4; ++mt)
                #pragma unroll
                for (int nt = 0; nt < 4; ++nt) {
                    mma_bf16(acc[mt][nt], ah[mt], bh[nt]);
                    mma_bf16(acc[mt][nt], ah[mt], bl[nt]);
                    mma_bf16(acc[mt][nt], al[mt], bh[nt]);
                }
        }
    }

    // epilogue: d2 = bb[m] - 2*dot
    const float* bbp = g_bb + branch * (BATCH * MPTS) + bz * MPTS;
    #pragma unroll
    for (int mt = 0; mt < 4; ++mt) {
        #pragma unroll
        for (int half = 0; half < 2; ++half) {
            int ns = by * 128 + wm + mt * 16 + g + half * 8;
            if (ns >= NSAMP) continue;
            float* orow = g_d2 + ((size_t)bz * NSAMP + ns) * MPTS;
            #pragma unroll
            for (int nt = 0; nt < 4; ++nt) {
                int mp = bx * 128 + wn + nt * 8 + tig * 2;
                if (mp < MPTS) {
                    float2 bbv = *reinterpret_cast<const float2*>(bbp + mp);
                    float2 o;
                    o.x = fmaf(-2.f, acc[mt][nt][half * 2 + 0], bbv.x);
                    o.y = fmaf(-2.f, acc[mt][nt][half * 2 + 1], bbv.y);
                    *reinterpret_cast<float2*>(orow + mp) = o;
                }
            }
        }
    }
}

// ---------- kernel 3: per-row exact k=1000 select + cosine reduction ----------
// 512 threads. Single-pass 12-bit histogram on normalized keys, block scan for
// the threshold bin, then COMPACT selected indices to smem and gather densely
// (independent LDGs -> full MLP, no conditional dependent-load chains).
#define STHR 512

__device__ __forceinline__ unsigned int ukey12(unsigned int kbits, float mn, float scale) {
    float f = (__uint_as_float(kbits) - mn) * scale;
    unsigned int u = __float2uint_rz(f);
    return u > 4095u ? 4095u : u;
}

__global__ __launch_bounds__(STHR) void select_reduce(const float* __restrict__ dist,
                                                      const int* __restrict__ ridx,
                                                      int branch) {
    __shared__ __align__(16) unsigned int keys[MPTS];
    __shared__ unsigned int hist[4096];
    __shared__ int list[KNN];
    __shared__ float wred[32];
    __shared__ float sh_mn, sh_scale;
    __shared__ unsigned int wtot[16];
    __shared__ unsigned int sh_T;
    __shared__ int sh_r;
    __shared__ int sh_eq;
    __shared__ int sh_cnt;
    __shared__ float red[48];

    int tid = threadIdx.x;
    int lane = tid & 31;
    int w = tid >> 5;
    int b = blockIdx.x / NSAMP;
    int n = blockIdx.x % NSAMP;
    int col = ridx[n];
    float aa = g_bb[branch * (BATCH * MPTS) + b * MPTS + col];
    const float* rowp = g_d2 + (size_t)blockIdx.x * MPTS;

    for (int j = tid; j < 4096 / 4; j += STHR)
        reinterpret_cast<uint4*>(hist)[j] = make_uint4(0u, 0u, 0u, 0u);
    float lmn = 3.4e38f, lmx = 0.f;
    for (int q = tid; q < MPTS / 4; q += STHR) {
        float4 v = reinterpret_cast<const float4*>(rowp)[q];
        float x0 = fmaxf(v.x + aa, 0.f), x1 = fmaxf(v.y + aa, 0.f);
        float x2 = fmaxf(v.z + aa, 0.f), x3 = fmaxf(v.w + aa, 0.f);
        uint4 k;
        k.x = __float_as_uint(x0); k.y = __float_as_uint(x1);
        k.z = __float_as_uint(x2); k.w = __float_as_uint(x3);
        reinterpret_cast<uint4*>(keys)[q] = k;
        lmn = fminf(lmn, fminf(fminf(x0, x1), fminf(x2, x3)));
        lmx = fmaxf(lmx, fmaxf(fmaxf(x0, x1), fmaxf(x2, x3)));
    }
    lmn = warp_min(lmn);
    lmx = warp_max(lmx);
    if (lane == 0) { wred[w] = lmn; wred[16 + w] = lmx; }
    if (tid == 0) { sh_eq = 0; sh_cnt = 0; }
    __syncthreads();
    if (tid == 0) {
        float mn = wred[0], mx = wred[16];
        #pragma unroll
        for (int i = 1; i < 16; i++) { mn = fminf(mn, wred[i]); mx = fmaxf(mx, wred[16 + i]); }
        sh_mn = mn;
        sh_scale = 4095.0f / fmaxf(mx - mn, 1e-30f);
    }
    __syncthreads();
    float mn = sh_mn, scale = sh_scale;

    for (int i = tid; i < MPTS; i += STHR)
        atomicAdd(&hist[ukey12(keys[i], mn, scale)], 1u);
    __syncthreads();

    // block scan over 4096 bins, 8 per thread
    {
        unsigned int c[8];
        unsigned int s = 0;
        int base = tid * 8;
        #pragma unroll
        for (int j = 0; j < 8; j++) { c[j] = hist[base + j]; s += c[j]; }
        unsigned int inc = s;
        #pragma unroll
        for (int o = 1; o < 32; o <<= 1) {
            unsigned int v = __shfl_up_sync(0xffffffffu, inc, o);
            if (lane >= o) inc += v;
        }
        if (lane == 31) wtot[w] = inc;
        __syncthreads();
        if (tid == 0) {
            unsigned int t = 0;
            #pragma unroll
            for (int i = 0; i < 16; i++) { unsigned int v = wtot[i]; wtot[i] = t; t += v; }
        }
        __syncthreads();
        unsigned int excl = wtot[w] + inc - s;
        if (KNN > excl && KNN <= excl + s) {
            unsigned int cum = excl;
            #pragma unroll
            for (int j = 0; j < 8; j++) {
                if (cum + c[j] >= KNN) { sh_T = (unsigned int)(base + j); sh_r = (int)(KNN - cum); break; }
                cum += c[j];
            }
        }
    }
    __syncthreads();
    unsigned int T = sh_T;
    int need_eq = sh_r;

    // compact selected indices (exactly KNN of them) into smem list
    for (int i = tid; i < MPTS; i += STHR) {
        unsigned int u = ukey12(keys[i], mn, scale);
        bool take = (u < T);
        if (!take && u == T) take = (atomicAdd(&sh_eq, 1) < need_eq);
        if (take) list[atomicAdd(&sh_cnt, 1)] = i;
    }
    __syncthreads();

    // dense gather: independent LDGs, full MLP
    const float* dcol = dist + (size_t)b * MPTS * MPTS + col;
    float num = 0.f, s1 = 0.f, s2 = 0.f;
    for (int j = tid; j < KNN; j += STHR) {
        int i = list[j];
        float dr = sqrtf(fmaxf(__uint_as_float(keys[i]), 1e-12f));
        float df = __ldg(dcol + (size_t)i * MPTS);
        num = fmaf(dr, df, num);
        s1  = fmaf(dr, dr, s1);
        s2  = fmaf(df, df, s2);
    }
    num = warp_sum(num); s1 = warp_sum(s1); s2 = warp_sum(s2);
    if (lane == 0) { red[w] = num; red[16 + w] = s1; red[32 + w] = s2; }
    __syncthreads();
    if (tid == 0) {
        float N = 0.f, S1 = 0.f, S2 = 0.f;
        #pragma unroll
        for (int i = 0; i < 16; i++) { N += red[i]; S1 += red[16 + i]; S2 += red[32 + i]; }
        float den = fmaxf(sqrtf(S1), EPSF) * fmaxf(sqrtf(S2), EPSF);
        float sim = 1.f - fabsf(N / den);
        atomicAdd(&g_acc[0], sim);
    }
}

// ---------- kernel 4: ortho / bij / res losses ----------
__global__ void small_losses(const float* __restrict__ A0, const float* __restrict__ A1,
                             const float* __restrict__ A2, const float* __restrict__ A3) {
    __shared__ float shA[KSPP * KSPP];
    __shared__ float shB[KSPP * KSPP];
    __shared__ float red[8];
    int t = blockIdx.x, b = blockIdx.y, tid = threadIdx.x;
    const float* mats[4] = {A0, A1, A2, A3};
    size_t off = (size_t)b * KSPP * KSPP;
    float local = 0.f;
    if (t == 6) {
        for (int e = tid; e < KSPP * KSPP; e += 256) {
            float d1 = A0[off + e] - A2[off + e];
            float d2 = A1[off + e] - A3[off + e];
            local += d1 * d1 + d2 * d2;
        }
    } else {
        int ai, bi; bool tb;
        switch (t) {
            case 0: ai = 0; bi = 0; tb = true;  break;
            case 1: ai = 1; bi = 1; tb = true;  break;
            case 2: ai = 2; bi = 2; tb = true;  break;
            case 3: ai = 3; bi = 3; tb = true;  break;
            case 4: ai = 0; bi = 1; tb = false; break;
            default: ai = 1; bi = 0; tb = false; break;
        }
        for (int e = tid; e < KSPP * KSPP; e += 256) {
            shA[e] = mats[ai][off + e];
            shB[e] = mats[bi][off + e];
        }
        __syncthreads();
        for (int e = tid; e < KSPP * KSPP; e += 256) {
            int i = e / KSPP, j = e % KSPP;
            float dot = 0.f;
            if (tb) {
                for (int k = 0; k < KSPP; k++) dot = fmaf(shA[i * KSPP + k], shB[j * KSPP + k], dot);
            } else {
                for (int k = 0; k < KSPP; k++) dot = fmaf(shA[i * KSPP + k], shB[k * KSPP + j], dot);
            }
            float diff = dot - (i == j ? 1.f : 0.f);
            local += diff * diff;
        }
    }
    local = warp_sum(local);
    if ((tid & 31) == 0) red[tid >> 5] = local;
    __syncthreads();
    if (tid == 0) {
        float s = 0.f;
        #pragma unroll
        for (int i = 0; i < 8; i++) s += red[i];
        int slot = (t < 4) ? 1 : ((t < 6) ? 2 : 3);
        atomicAdd(&g_acc[slot], s);
    }
}

// ---------- kernel 5: combine ----------
__global__ void finalize(float* __restrict__ out) {
    float dist  = g_acc[0] * 0.5f;
    float ortho = g_acc[1] / (float)BATCH * 0.5f;
    float bij   = g_acc[2] / (float)BATCH;
    float res   = g_acc[3] / (float)BATCH;
    out[0] = dist + ortho + bij + res;
    out[1] = ortho;
    out[2] = bij;
    out[3] = res;
    out[4] = dist;
}

extern "C" void kernel_launch(void* const* d_in, const int* in_sizes, int n_in,
                              void* d_out, int out_size) {
    const float* C12   = (const float*)d_in[0];
    const float* C21   = (const float*)d_in[1];
    const float* C12n  = (const float*)d_in[2];
    const float* C21n  = (const float*)d_in[3];
    const float* feat1 = (const float*)d_in[4];
    const float* feat2 = (const float*)d_in[5];
    const float* dist1 = (const float*)d_in[8];
    const float* dist2 = (const float*)d_in[9];
    const int*   ri1   = (const int*)d_in[10];
    const int*   ri2   = (const int*)d_in[11];
    float* out = (float*)d_out;

    static bool attr_set = false;
    if (!attr_set) {
        cudaFuncSetAttribute(gemm_mma, cudaFuncAttributeMaxDynamicSharedMemorySize,
                             SMEM_MMA_BYTES);
        attr_set = true;
    }

    init_norms<<<2500, 256>>>(feat1, feat2);

    dim3 tg((MPTS + 127) / 128, (NSAMP + 127) / 128, BATCH);   // 40 x 16 x 2
    gemm_mma<<<tg, 256, SMEM_MMA_BYTES>>>(feat1, ri1, 0);
    select_reduce<<<BATCH * NSAMP, STHR>>>(dist1, ri1, 0);
    gemm_mma<<<tg, 256, SMEM_MMA_BYTES>>>(feat2, ri2, 1);
    select_reduce<<<BATCH * NSAMP, STHR>>>(dist2, ri2, 1);

    small_losses<<<dim3(7, BATCH), 256>>>(C12, C21, C12n, C21n);
    finalize<<<1, 1>>>(out);
}